// round 8
// baseline (speedup 1.0000x reference)
#include <cuda_runtime.h>
#include <cuda_bf16.h>
#include <stdint.h>
#include <math.h>

// ---------------------------------------------------------------------------
// Problem constants
// ---------------------------------------------------------------------------
#define NUM_CLASSES 10
#define DD     64
#define MAXB   1024
#define NE_PAD 50048           // 391 tiles of 128
#define GAMMA  1.0f
#define EPS    1e-12f

// Tiling (mma.sync path — tcgen05 is 'a'-gated; harness emits compute_103)
#define TM 128
#define TN 128
#define GCOLS 37               // grid = 8 x 37 = 296 CTAs = 2/SM, one wave
#define ROWB 144               // smem row stride in bytes (64 bf16 + 8 pad)

#define SM_A   0
#define SM_B0  (TM * ROWB)             // 18432
#define SM_B1  (SM_B0 + TN * ROWB)     // 36864
#define SM_TOT (SM_B1 + TN * ROWB)     // 55296 (dynamic: > 48KB static cap)

#define MAXSURV (1u * 1024u * 1024u)

// ---------------------------------------------------------------------------
// Scratch (__device__ globals; no cudaMalloc allowed)
// ---------------------------------------------------------------------------
__device__ __nv_bfloat16 g_ebf[(size_t)NE_PAD * DD];
__device__ __nv_bfloat16 g_xbf[(size_t)MAXB * DD];
__device__ float g_e2[NE_PAD];
__device__ float g_x2[MAXB];
__device__ float g_class[MAXB * NUM_CLASSES];
__device__ float g_beta;
__device__ unsigned int g_nsurv;
__device__ unsigned int g_done;
__device__ unsigned int g_surv[MAXSURV];

// ---------------------------------------------------------------------------
// PTX helpers (baseline ISA only: ldmatrix, mma.sync, cp.async)
// ---------------------------------------------------------------------------
__device__ __forceinline__ uint32_t smem_to_u32(const void* p) {
    uint32_t a;
    asm("{ .reg .u64 t; cvta.to.shared.u64 t, %1; cvt.u32.u64 %0, t; }"
        : "=r"(a) : "l"(p));
    return a;
}
__device__ __forceinline__ void ldsm_x4(uint32_t* r, uint32_t addr) {
    asm volatile("ldmatrix.sync.aligned.m8n8.x4.shared.b16 {%0,%1,%2,%3}, [%4];"
                 : "=r"(r[0]), "=r"(r[1]), "=r"(r[2]), "=r"(r[3]) : "r"(addr));
}
__device__ __forceinline__ void ldsm_x2(uint32_t* r, uint32_t addr) {
    asm volatile("ldmatrix.sync.aligned.m8n8.x2.shared.b16 {%0,%1}, [%2];"
                 : "=r"(r[0]), "=r"(r[1]) : "r"(addr));
}
__device__ __forceinline__ void mma_bf16(float* c, const uint32_t* a,
                                         const uint32_t* b) {
    asm volatile(
        "mma.sync.aligned.m16n8k16.row.col.f32.bf16.bf16.f32 "
        "{%0,%1,%2,%3}, {%4,%5,%6,%7}, {%8,%9}, {%0,%1,%2,%3};"
        : "+f"(c[0]), "+f"(c[1]), "+f"(c[2]), "+f"(c[3])
        : "r"(a[0]), "r"(a[1]), "r"(a[2]), "r"(a[3]), "r"(b[0]), "r"(b[1]));
}
__device__ __forceinline__ void cp_async16(uint32_t dst, const void* src) {
    asm volatile("cp.async.cg.shared.global [%0], [%1], 16;"
                 :: "r"(dst), "l"(src) : "memory");
}
__device__ __forceinline__ void cp_commit() {
    asm volatile("cp.async.commit_group;" ::: "memory");
}
template <int N>
__device__ __forceinline__ void cp_wait() {
    asm volatile("cp.async.wait_group %0;" :: "n"(N) : "memory");
}

// ---------------------------------------------------------------------------
// Prep: norms, bf16 conversion (padded), beta = softplus(beta_raw), zero bins.
// 8 threads per row (8 floats each) — 2x the MLP of R7's version.
// ---------------------------------------------------------------------------
__global__ void prep_kernel(const float* __restrict__ x,
                            const float* __restrict__ ex,
                            const float* __restrict__ beta_raw,
                            int B, int NE) {
    const int t = threadIdx.x;
    const int gid = blockIdx.x * 256 + t;
    if (gid < MAXB * NUM_CLASSES) g_class[gid] = 0.f;
    if (gid == 0) {
        float br = beta_raw[0];
        g_beta = (br > 20.f) ? br : log1pf(expf(br));
        g_nsurv = 0u;
        g_done  = 0u;
    }
    const int R = blockIdx.x * 32 + (t >> 3);   // padded row index
    const int part = t & 7;                      // 8-float segment
    bool is_x = false;
    int outr = R;
    const float* src = nullptr;
    if (R < NE_PAD) {
        if (R < NE) src = ex + (size_t)R * DD + part * 8;
    } else {
        int xr = R - NE_PAD;
        if (xr >= MAXB) return;
        is_x = true; outr = xr;
        if (xr < B) src = x + (size_t)xr * DD + part * 8;
    }
    float v[8];
    float s = 0.f;
    if (src) {
        #pragma unroll
        for (int q = 0; q < 2; q++) {
            float4 f = ((const float4*)src)[q];
            v[4*q+0] = f.x; v[4*q+1] = f.y; v[4*q+2] = f.z; v[4*q+3] = f.w;
            s += f.x*f.x + f.y*f.y + f.z*f.z + f.w*f.w;
        }
    } else {
        #pragma unroll
        for (int q = 0; q < 8; q++) v[q] = 0.f;
    }
    s += __shfl_xor_sync(0xFFFFFFFFu, s, 1);
    s += __shfl_xor_sync(0xFFFFFFFFu, s, 2);
    s += __shfl_xor_sync(0xFFFFFFFFu, s, 4);
    alignas(16) __nv_bfloat16 hb[8];
    #pragma unroll
    for (int q = 0; q < 8; q++) hb[q] = __float2bfloat16(v[q]);
    __nv_bfloat16* dst =
        (is_x ? (g_xbf + (size_t)outr * DD) : (g_ebf + (size_t)outr * DD)) + part * 8;
    ((uint4*)dst)[0] = ((uint4*)hb)[0];
    if (part == 0) {
        if (is_x) g_x2[outr] = (outr < B) ? s : 0.f;
        else      g_e2[outr] = (outr < NE) ? s : 3.0e8f;  // padding: gate never fires
    }
}

// ---------------------------------------------------------------------------
// Main: HMMA filter GEMM with cp.async double-buffered B tiles.
// Gate -> 64-bit mask -> (rare) direct global survivor push. No smem queue.
// ---------------------------------------------------------------------------
__global__ void __launch_bounds__(256, 2)
exemplar_mma_kernel(int B, int NE) {
    extern __shared__ char smem[];
    const uint32_t saU = smem_to_u32(smem) + SM_A;
    const uint32_t sb0 = smem_to_u32(smem) + SM_B0;
    const uint32_t sb1 = smem_to_u32(smem) + SM_B1;

    const int t = threadIdx.x;
    const int wid = t >> 5, lane = t & 31;
    const int warpM = wid >> 2;            // 0..1
    const int warpN = wid & 3;             // 0..3
    const int bm = blockIdx.y * TM;
    const int NT = (NE + TN - 1) / TN;

    // Load A tile (128 rows x 64 bf16) once (plain LDG/STS; first sync covers).
    for (int i = t; i < TM * 8; i += 256) {
        int r = i >> 3, c = i & 7;
        *(uint4*)(smem + SM_A + r * ROWB + c * 16) =
            *(const uint4*)(g_xbf + (size_t)(bm + r) * DD + c * 8);
    }

    // ldmatrix lane-address components
    const int rowA = (lane & 7) + ((lane >> 3) & 1) * 8;
    const int kA   = ((lane >> 4) & 1) * 8;
    const int l16  = lane & 15;
    const int rowBf = l16 & 7;
    const int kB    = ((l16 >> 3) & 1) * 8;

    uint32_t aAddr[4];
    #pragma unroll
    for (int mi = 0; mi < 4; mi++)
        aAddr[mi] = saU + (uint32_t)(warpM * 64 + mi * 16 + rowA) * ROWB + kA * 2;
    uint32_t bOff[4];
    #pragma unroll
    for (int ni = 0; ni < 4; ni++)
        bOff[ni] = (uint32_t)(warpN * 32 + ni * 8 + rowBf) * ROWB + kB * 2;

    const float beta = g_beta;
    const float thr  = 60.f / beta + 2.f;   // margin 2 >> bf16 dot err (~0.35)

    float x2a[4], x2b[4];
    #pragma unroll
    for (int mi = 0; mi < 4; mi++) {
        int r0 = bm + warpM * 64 + mi * 16 + (lane >> 2);
        x2a[mi] = g_x2[r0];
        x2b[mi] = g_x2[r0 + 8];
    }

    // cp.async B-tile issue: 4 x 16B per thread (1024 chunks per tile).
    const int pr = t >> 1;                 // rows 0..127 (2 threads/row)
    const int pc = (t & 1) * 2;            // chunk pairs: c, c+1 then c+4, c+5
    auto issue_b = [&](uint32_t sbase, int bn) {
        const __nv_bfloat16* src = g_ebf + (size_t)(bn + pr) * DD;
        uint32_t drow = sbase + (uint32_t)pr * ROWB;
        cp_async16(drow + (pc + 0) * 16, src + (pc + 0) * 8);
        cp_async16(drow + (pc + 1) * 16, src + (pc + 1) * 8);
        cp_async16(drow + (pc + 4) * 16, src + (pc + 4) * 8);
        cp_async16(drow + (pc + 5) * 16, src + (pc + 5) * 8);
    };

    // Prologue: prefetch first tile.
    issue_b(sb0, blockIdx.x * TN);
    cp_commit();

    int it = 0;
    for (int et = blockIdx.x; et < NT; et += GCOLS, it++) {
        const int bn = et * TN;
        const uint32_t cur = (it & 1) ? sb1 : sb0;
        const uint32_t nxt = (it & 1) ? sb0 : sb1;
        const int etn = et + GCOLS;
        if (etn < NT) {
            issue_b(nxt, etn * TN);
            cp_commit();
            cp_wait<1>();
        } else {
            cp_wait<0>();
        }
        __syncthreads();   // cur tile visible to all; prev reads of nxt done

        // e2 for this thread's 8 columns (L2/L1 hits).
        float2 e2p[4];
        #pragma unroll
        for (int ni = 0; ni < 4; ni++)
            e2p[ni] = *(const float2*)&g_e2[bn + warpN * 32 + ni * 8 + 2 * (lane & 3)];

        float acc[4][4][4];
        #pragma unroll
        for (int mi = 0; mi < 4; mi++)
            #pragma unroll
            for (int ni = 0; ni < 4; ni++)
                #pragma unroll
                for (int r = 0; r < 4; r++) acc[mi][ni][r] = 0.f;

        #pragma unroll
        for (int ks = 0; ks < 4; ks++) {
            const int k0b = ks * 32;
            uint32_t af[4][4];
            #pragma unroll
            for (int mi = 0; mi < 4; mi++) ldsm_x4(af[mi], aAddr[mi] + k0b);
            uint32_t bf[4][2];
            #pragma unroll
            for (int ni = 0; ni < 4; ni++) ldsm_x2(bf[ni], cur + bOff[ni] + k0b);
            #pragma unroll
            for (int mi = 0; mi < 4; mi++)
                #pragma unroll
                for (int ni = 0; ni < 4; ni++)
                    mma_bf16(acc[mi][ni], af[mi], bf[ni]);
        }

        // Branchless gate -> 64-bit survivor mask.
        uint32_t m0 = 0u, m1 = 0u;
        #pragma unroll
        for (int mi = 0; mi < 4; mi++) {
            #pragma unroll
            for (int ni = 0; ni < 4; ni++) {
                #pragma unroll
                for (int r = 0; r < 4; r++) {
                    float x2v = (r >= 2) ? x2b[mi] : x2a[mi];
                    float e2v = (r & 1) ? e2p[ni].y : e2p[ni].x;
                    float d2a = x2v + e2v - 2.f * acc[mi][ni][r];
                    uint32_t p = (d2a < thr) ? 1u : 0u;
                    int idx = (mi * 4 + ni) * 4 + r;
                    if (idx < 32) m0 |= p << idx;
                    else          m1 |= p << (idx - 32);
                }
            }
        }

        // Very rare: push packed (row,col) survivors straight to global queue.
        if (m0 | m1) {
            int cnt = __popc(m0) + __popc(m1);
            unsigned int base = atomicAdd(&g_nsurv, (unsigned)cnt);
            const int rbase = bm + warpM * 64 + (lane >> 2);
            const int cbase = bn + warpN * 32 + 2 * (lane & 3);
            #pragma unroll
            for (int half = 0; half < 2; half++) {
                uint32_t m = half ? m1 : m0;
                while (m) {
                    int i = __ffs(m) - 1;
                    m &= m - 1;
                    int r  = i & 3;
                    int ni = (i >> 2) & 3;
                    int mi = (i >> 4) + half * 2;
                    int row = rbase + mi * 16 + ((r >> 1) << 3);
                    int col = cbase + ni * 8 + (r & 1);
                    if (base < MAXSURV)
                        g_surv[base] = ((unsigned)row << 16) | (unsigned)col;
                    base++;
                }
            }
        }
        __syncthreads();   // all reads of cur done before it is re-prefetched
    }
}

// ---------------------------------------------------------------------------
// Survivors: exact fp32 recompute + exp + scatter-add. Last block finalizes
// logits = GAMMA * log(class_sims + EPS).
// ---------------------------------------------------------------------------
__global__ void survivor_finalize_kernel(const float* __restrict__ x,
                                         const float* __restrict__ ex,
                                         const int* __restrict__ labels,
                                         float* __restrict__ out,
                                         int B, int NE, int nout) {
    unsigned int n = g_nsurv;
    if (n > MAXSURV) n = MAXSURV;
    const float beta = g_beta;
    for (unsigned int i = blockIdx.x * blockDim.x + threadIdx.x; i < n;
         i += gridDim.x * blockDim.x) {
        unsigned int p = g_surv[i];
        int row = (int)(p >> 16);
        int col = (int)(p & 0xFFFFu);
        if (row >= B || col >= NE) continue;
        const float* xr = x  + (size_t)row * DD;
        const float* er = ex + (size_t)col * DD;
        float s = 0.f;
        #pragma unroll
        for (int q = 0; q < DD / 4; q++) {
            float4 a = ((const float4*)xr)[q];
            float4 e = ((const float4*)er)[q];
            s += a.x*e.x + a.y*e.y + a.z*e.z + a.w*e.w;
        }
        float d2 = fmaxf(g_x2[row] + g_e2[col] - 2.f * s, 0.f);
        float bd = beta * d2;
        // skipped mass <= NE*exp(-60) << 1e-3 * EPS
        if (bd < 60.f)
            atomicAdd(&g_class[row * NUM_CLASSES + labels[col]], expf(-bd));
    }

    // Last-block-done finalize (fuses the old finalize kernel's launch away).
    __shared__ unsigned int s_last;
    __threadfence();
    __syncthreads();
    if (threadIdx.x == 0)
        s_last = (atomicAdd(&g_done, 1u) == gridDim.x - 1) ? 1u : 0u;
    __syncthreads();
    if (s_last) {
        __threadfence();
        for (int i = threadIdx.x; i < nout; i += blockDim.x)
            out[i] = GAMMA * logf(g_class[i] + EPS);
    }
}

// ---------------------------------------------------------------------------
extern "C" void kernel_launch(void* const* d_in, const int* in_sizes, int n_in,
                              void* d_out, int out_size) {
    const float* x        = (const float*)d_in[0];
    const float* ex       = (const float*)d_in[1];
    const int*   labels   = (const int*)d_in[2];
    const float* beta_raw = (const float*)d_in[3];
    float* out = (float*)d_out;

    const int B  = in_sizes[0] / DD;
    const int NE = in_sizes[1] / DD;

    const int prep_blocks = (NE_PAD + MAXB) / 32;   // 1596
    prep_kernel<<<prep_blocks, 256>>>(x, ex, beta_raw, B, NE);

    static int smem_set = 0;
    if (!smem_set) {
        cudaFuncSetAttribute(exemplar_mma_kernel,
                             cudaFuncAttributeMaxDynamicSharedMemorySize, SM_TOT);
        smem_set = 1;
    }
    dim3 grid(GCOLS, (B + TM - 1) / TM);            // 37 x 8
    exemplar_mma_kernel<<<grid, 256, SM_TOT>>>(B, NE);

    survivor_finalize_kernel<<<148, 256>>>(x, ex, labels, out, B, NE, out_size);
}